// round 8
// baseline (speedup 1.0000x reference)
#include <cuda_runtime.h>
#include <math.h>

// ---------------------------------------------------------------------------
// QNetBlock: 18-qubit state-vector sim, batch 32.  3-pass schedule:
//  A: Phi_in,lo(L0) + RY(L0) bits 0..11            (contiguous 4096 chunks)
//  B: Phi_in,hi(L0)*Phi_out,lo(L0) + RY(L0) 12..17 + Phi_out,hi(L0)
//     + P1 relabel (in-CTA, key = tg bits {0..5,12..17})
//     + Phi_in(L1) + RY(L1) tg bits {1..4,12..17}  (10 levels in key space)
//  C: RY(L1) tg bits {0,5..11} + P2 scatter + |amp|/||x|| -> out
// Validity of B: CNOT-ring columns m[q]^m[q-1]=e_q, so source span
// {0..4,11..17} has target span containing e1..e4,e12..e17; target bits
// 5..11 collapse to tfixB{5..11} ^ c11*0x7F (c11 = tg5^tfixB5).
// ---------------------------------------------------------------------------

#define NB      32
#define NSTATE  (1 << 18)
#define CHUNK   4096
#define NCHK    64

typedef unsigned long long u64;

__device__ u64   g_sa[(size_t)NB * NSTATE];   // 64 MB
__device__ u64   g_sb[(size_t)NB * NSTATE];   // 64 MB
__device__ float g_partial[NB * NCHK];
__device__ float g_invnorm[NB];

struct PermM { unsigned m[18]; };

// ---- packed f32x2 helpers --------------------------------------------------
__device__ __forceinline__ u64 pk(float x, float y) {
    u64 r; asm("mov.b64 %0,{%1,%2};" : "=l"(r) : "f"(x), "f"(y)); return r;
}
__device__ __forceinline__ void up(u64 a, float& x, float& y) {
    asm("mov.b64 {%0,%1},%2;" : "=f"(x), "=f"(y) : "l"(a));
}
__device__ __forceinline__ u64 f2mul(u64 a, u64 b) {
    u64 r; asm("mul.rn.f32x2 %0,%1,%2;" : "=l"(r) : "l"(a), "l"(b)); return r;
}
__device__ __forceinline__ u64 f2fma(u64 a, u64 b, u64 c) {
    u64 r; asm("fma.rn.f32x2 %0,%1,%2,%3;" : "=l"(r) : "l"(a), "l"(b), "l"(c)); return r;
}
__device__ __forceinline__ u64 cmulp(u64 a, u64 b) {
    float ax, ay, bx, by; up(a, ax, ay); up(b, bx, by);
    return pk(fmaf(ax, bx, -ay * by), fmaf(ax, by, ay * bx));
}
__device__ __forceinline__ void bfly2(u64& A, u64& B, u64 c2, u64 s2, u64 ns2) {
    u64 tA = f2mul(ns2, B);
    u64 tB = f2mul(c2,  B);
    u64 nA = f2fma(c2, A, tA);
    B      = f2fma(s2, A, tB);
    A      = nA;
}

// swizzles (conflict-free for all ownership patterns in each space)
__device__ __forceinline__ int sw16(int i) { return i ^ ((i >> 4) & 15); }          // pass A
__device__ __forceinline__ int swB(int i)  { return i ^ (((i >> 5) & 0xF) << 1); }  // pass B
__device__ __forceinline__ int swC(int i)  { return i ^ ((i >> 5) & 1); }           // pass C

// ---------------------------------------------------------------------------
// Pass A: L0 RY bits 0..11 + Phi_in,lo(L0) at load; reads x, emits sum(x^2).
// ---------------------------------------------------------------------------
__global__ void __launch_bounds__(256, 3)
passA(const float* __restrict__ x, const float* __restrict__ params,
      u64* __restrict__ dst)
{
    extern __shared__ u64 smem[];          // 4096 u64 = 32 KB
    __shared__ float sp[54];
    __shared__ u64   C2[12], S2[12], NS2[12], Tin[16];
    __shared__ float wsum[8];

    int t  = threadIdx.x;
    int b  = blockIdx.x >> 6;
    int ch = blockIdx.x & 63;
    int base = b * NSTATE + ch * CHUNK;

    float xr[16];
    float ss = 0.f;
#pragma unroll
    for (int k = 0; k < 16; k++) {
        float xv = x[base + t + 256 * k];
        xr[k] = xv;
        ss += xv * xv;
    }
#pragma unroll
    for (int o = 16; o; o >>= 1) ss += __shfl_down_sync(0xffffffffu, ss, o);
    if ((t & 31) == 0) wsum[t >> 5] = ss;
    if (t < 54) sp[t] = params[t];
    __syncthreads();

    if (t == 0) {
        float s = 0.f;
        for (int i = 0; i < 8; i++) s += wsum[i];
        g_partial[blockIdx.x] = s;         // deterministic fixed-order sum
    }

    if (t < 12) {                          // RY for bit p = t (wire 17-t)
        float s, c; sincosf(0.5f * sp[(17 - t) * 3 + 1], &s, &c);
        C2[t] = pk(c, c); S2[t] = pk(s, s); NS2[t] = pk(-s, -s);
    } else if (t >= 32 && t < 48) {        // Phi_in table over bits 8..11
        int k = t - 32; float a = 0.f;
#pragma unroll
        for (int j = 0; j < 4; j++)
            if ((k >> j) & 1) a += sp[(17 - (8 + j)) * 3 + 0];
        float s, c; sincosf(a, &s, &c); Tin[k] = pk(c, s);
    }
    float ang = 0.f;
#pragma unroll
    for (int p = 0; p < 12; p++) {
        float ph = sp[(17 - p) * 3 + 0];
        ang -= 0.5f * ph;
        if (p < 8 && ((t >> p) & 1)) ang += ph;
    }
    float fs, fc; sincosf(ang, &fs, &fc);
    u64 pf0 = pk(fc, fs);
    __syncthreads();

    u64 v[16];
#pragma unroll
    for (int k = 0; k < 16; k++)           // real input: one packed mul
        v[k] = f2mul(pk(xr[k], xr[k]), cmulp(pf0, Tin[k]));

    // A: RY bits 8..11
#pragma unroll
    for (int kb = 0; kb < 4; kb++) {
        int m = 1 << kb;
        u64 c2 = C2[8 + kb], s2 = S2[8 + kb], n2 = NS2[8 + kb];
#pragma unroll
        for (int k = 0; k < 16; k++)
            if (!(k & m)) bfly2(v[k], v[k + m], c2, s2, n2);
    }
#pragma unroll
    for (int k = 0; k < 16; k++) smem[sw16(t + 256 * k)] = v[k];
    __syncthreads();

    // B: RY bits 0..3
#pragma unroll
    for (int k = 0; k < 16; k++) v[k] = smem[sw16(t * 16 + k)];
#pragma unroll
    for (int kb = 0; kb < 4; kb++) {
        int m = 1 << kb;
        u64 c2 = C2[kb], s2 = S2[kb], n2 = NS2[kb];
#pragma unroll
        for (int k = 0; k < 16; k++)
            if (!(k & m)) bfly2(v[k], v[k + m], c2, s2, n2);
    }
#pragma unroll
    for (int k = 0; k < 16; k++) smem[sw16(t * 16 + k)] = v[k];
    __syncthreads();

    // C: RY bits 4..7, coalesced store
    int r = t & 15, h = t >> 4;
#pragma unroll
    for (int k = 0; k < 16; k++) v[k] = smem[sw16(r + 16 * k + 256 * h)];
#pragma unroll
    for (int kb = 0; kb < 4; kb++) {
        int m = 1 << kb;
        u64 c2 = C2[4 + kb], s2 = S2[4 + kb], n2 = NS2[4 + kb];
#pragma unroll
        for (int k = 0; k < 16; k++)
            if (!(k & m)) bfly2(v[k], v[k + m], c2, s2, n2);
    }
#pragma unroll
    for (int k = 0; k < 16; k++)
        dst[base + r + 16 * k + 256 * h] = v[k];
}

// ---------------------------------------------------------------------------
// Pass B: fused L0-high + P1 + L1 partial. Source span free bits {0..4,11..17},
// fixed src bits 5..10 per block.
// ---------------------------------------------------------------------------
__global__ void __launch_bounds__(256, 3)
passB(const float* __restrict__ p0, const float* __restrict__ p1, PermM P,
      const u64* __restrict__ src, u64* __restrict__ dst)
{
    extern __shared__ u64 sm[];            // 4096 u64 = 32 KB
    __shared__ float sp[54], sq[54];
    __shared__ u64 CL[6], SL[6], NL[6];    // L0 RY, src bits 12..17
    __shared__ u64 CA[4], SA[4], NA[4];    // L1 RY, tg bits 12..15
    __shared__ u64 CB[4], SB[4], NB2[4];   // L1 RY, tg bits 1..4
    __shared__ u64 CC[2], SC[2], NC[2];    // L1 RY, tg bits 16..17
    __shared__ u64 Hin[64], Hout[64], TinB[16];

    int t   = threadIdx.x;
    int b   = blockIdx.x >> 6;
    int fix = blockIdx.x & 63;             // src bits 5..10

    int base = b * NSTATE + ((t & 31) | (fix << 5) | (((t >> 5) & 1) << 11)
                             | ((t >> 6) << 16));
    u64 v[16];
#pragma unroll
    for (int k = 0; k < 16; k++) v[k] = src[base + (k << 12)];  // coalesced

    if (t < 54) sp[t] = p0[t];
    else if (t >= 64 && t < 118) sq[t - 64] = p1[t - 64];
    __syncthreads();

    // tables
    if (t < 6) {                           // L0 RY src bit 12+t (wire 5-t)
        float s, c; sincosf(0.5f * sp[(5 - t) * 3 + 1], &s, &c);
        CL[t] = pk(c, c); SL[t] = pk(s, s); NL[t] = pk(-s, -s);
    } else if (t < 10) {                   // L1 RY tg bit 12+j (wire 5-j)
        int j = t - 6;
        float s, c; sincosf(0.5f * sq[(5 - j) * 3 + 1], &s, &c);
        CA[j] = pk(c, c); SA[j] = pk(s, s); NA[j] = pk(-s, -s);
    } else if (t < 14) {                   // L1 RY tg bit 1+j (wire 16-j)
        int j = t - 10;
        float s, c; sincosf(0.5f * sq[(16 - j) * 3 + 1], &s, &c);
        CB[j] = pk(c, c); SB[j] = pk(s, s); NB2[j] = pk(-s, -s);
    } else if (t < 16) {                   // L1 RY tg bit 16+j (wire 1-j)
        int j = t - 14;
        float s, c; sincosf(0.5f * sq[(1 - j) * 3 + 1], &s, &c);
        CC[j] = pk(c, c); SC[j] = pk(s, s); NC[j] = pk(-s, -s);
    } else if (t >= 160 && t < 176) {      // Phi_in(L1) over tg bits 12..15
        int kk = t - 160; float a = 0.f;
#pragma unroll
        for (int j = 0; j < 4; j++)
            if ((kk >> j) & 1) a += sq[(5 - j) * 3 + 0];
        float s, c; sincosf(a, &s, &c); TinB[kk] = pk(c, s);
    }
    if (t >= 64 && t < 128) {              // Phi_in,hi / Phi_out,hi (L0)
        int kk = t - 64;
        float ai = 0.f, ao = 0.f;
#pragma unroll
        for (int j = 0; j < 6; j++) {
            float ph = sp[(5 - j) * 3 + 0];
            float om = sp[(5 - j) * 3 + 2];
            ai -= 0.5f * ph;  ao -= 0.5f * om;
            if ((kk >> j) & 1) { ai += ph; ao += om; }
        }
        float s, c;
        sincosf(ai, &s, &c); Hin[kk]  = pk(c, s);
        sincosf(ao, &s, &c); Hout[kk] = pk(c, s);
    }
    // per-thread Phi_out,lo(L0): src bits 0..11 = t0..4 | fix | t5
    float ang = 0.f;
#pragma unroll
    for (int p = 0; p < 12; p++) {
        float om = sp[(17 - p) * 3 + 2];
        ang -= 0.5f * om;
        int bit = (p < 5) ? ((t >> p) & 1)
                : (p < 11 ? ((fix >> (p - 5)) & 1) : ((t >> 5) & 1));
        if (bit) ang += om;
    }
    float s0, c0; sincosf(ang, &s0, &c0);
    u64 pg = pk(c0, s0);
    __syncthreads();

    // load diag: Phi_out,lo(L0) * Phi_in,hi(L0); src12..17 = k | (t>>6)<<4
    int h2 = t >> 6;
#pragma unroll
    for (int k = 0; k < 16; k++)
        v[k] = cmulp(v[k], cmulp(pg, Hin[k | (h2 << 4)]));

    // L0 RY src bits 12..15 (k bits 0..3)
#pragma unroll
    for (int kb = 0; kb < 4; kb++) {
        int m = 1 << kb;
        u64 c2 = CL[kb], s2 = SL[kb], n2 = NL[kb];
#pragma unroll
        for (int k = 0; k < 16; k++)
            if (!(k & m)) bfly2(v[k], v[k + m], c2, s2, n2);
    }

    // T1: ell bits: 0..4=src0..4, 5=src11, 6..9=src12..15, 10..11=src16..17
#pragma unroll
    for (int k = 0; k < 16; k++)
        sm[swB((t & 31) | (((t >> 5) & 1) << 5) | (k << 6) | ((t >> 6) << 10))] = v[k];
    __syncthreads();

    // phase 2: ell = t | k<<8 ; k = src bits 14..17
#pragma unroll
    for (int k = 0; k < 16; k++) v[k] = sm[swB(t | (k << 8))];
    {   // L0 RY src16 (k bit 2), src17 (k bit 3)
        u64 c2 = CL[4], s2 = SL[4], n2 = NL[4];
#pragma unroll
        for (int k = 0; k < 16; k++)
            if (!(k & 4)) bfly2(v[k], v[k + 4], c2, s2, n2);
        c2 = CL[5]; s2 = SL[5]; n2 = NL[5];
#pragma unroll
        for (int k = 0; k < 16; k++)
            if (!(k & 8)) bfly2(v[k], v[k + 8], c2, s2, n2);
    }
    // Phi_out,hi(L0): src12..17 = ((t>>6)&3) | k<<2
#pragma unroll
    for (int k = 0; k < 16; k++)
        v[k] = cmulp(v[k], Hout[((t >> 6) & 3) | (k << 2)]);

    // relabel through P1: tg = XOR of column masks
    unsigned tfixB = 0;
#pragma unroll
    for (int j = 0; j < 6; j++)
        if ((fix >> j) & 1) tfixB ^= P.m[5 + j];
    unsigned tb = tfixB;
#pragma unroll
    for (int p = 0; p < 5; p++)
        if ((t >> p) & 1) tb ^= P.m[p];
    if ((t >> 5) & 1) tb ^= P.m[11];
    if ((t >> 6) & 1) tb ^= P.m[12];
    if ((t >> 7) & 1) tb ^= P.m[13];
    __syncthreads();                       // all reads done before key-writes
#pragma unroll
    for (int k = 0; k < 16; k++) {
        unsigned tg = tb;
        if (k & 1) tg ^= P.m[14];
        if (k & 2) tg ^= P.m[15];
        if (k & 4) tg ^= P.m[16];
        if (k & 8) tg ^= P.m[17];
        unsigned key = (tg & 0x3F) | (((tg >> 12) & 0x3F) << 6);
        sm[swB(key)] = v[k];
    }
    __syncthreads();

    // phase 3: key = (t&63)|k<<6|(t>>6)<<10 ; k = tg bits 12..15
#pragma unroll
    for (int k = 0; k < 16; k++)
        v[k] = sm[swB((t & 63) | (k << 6) | ((t >> 6) << 10))];
    // Phi_in(L1): angle linear in key bits
    float a2 = 0.f;
#pragma unroll
    for (int w = 0; w < 18; w++) a2 -= 0.5f * sq[w * 3];
#pragma unroll
    for (int q = 0; q < 5; q++)
        if ((t >> q) & 1) a2 += sq[(17 - q) * 3];
    int key5 = (t >> 5) & 1;
    if (key5) a2 += sq[12 * 3];            // tg bit 5, wire 12
    int c11 = key5 ^ ((tfixB >> 5) & 1);
#pragma unroll
    for (int q = 6; q < 12; q++)
        if ((((tfixB >> q) & 1) ^ c11)) a2 += sq[(17 - q) * 3];
    if ((t >> 6) & 1) a2 += sq[1 * 3];     // tg bit 16, wire 1
    if ((t >> 7) & 1) a2 += sq[0 * 3];     // tg bit 17, wire 0
    sincosf(a2, &s0, &c0);
    u64 pfi = pk(c0, s0);
#pragma unroll
    for (int k = 0; k < 16; k++)
        v[k] = cmulp(v[k], cmulp(pfi, TinB[k]));
    // L1 RY tg bits 12..15
#pragma unroll
    for (int kb = 0; kb < 4; kb++) {
        int m = 1 << kb;
        u64 c2 = CA[kb], s2 = SA[kb], n2 = NA[kb];
#pragma unroll
        for (int k = 0; k < 16; k++)
            if (!(k & m)) bfly2(v[k], v[k + m], c2, s2, n2);
    }
#pragma unroll
    for (int k = 0; k < 16; k++)
        sm[swB((t & 63) | (k << 6) | ((t >> 6) << 10))] = v[k];
    __syncthreads();

    // phase 4: key = (t&1)|k<<1|(t>>1)<<5 ; k = tg bits 1..4
#pragma unroll
    for (int k = 0; k < 16; k++)
        v[k] = sm[swB((t & 1) | (k << 1) | ((t >> 1) << 5))];
#pragma unroll
    for (int kb = 0; kb < 4; kb++) {
        int m = 1 << kb;
        u64 c2 = CB[kb], s2 = SB[kb], n2 = NB2[kb];
#pragma unroll
        for (int k = 0; k < 16; k++)
            if (!(k & m)) bfly2(v[k], v[k + m], c2, s2, n2);
    }
#pragma unroll
    for (int k = 0; k < 16; k++)
        sm[swB((t & 1) | (k << 1) | ((t >> 1) << 5))] = v[k];
    __syncthreads();

    // phase 5: key = t | k<<8 ; k = tg bits 14..17; levels on 16,17
#pragma unroll
    for (int k = 0; k < 16; k++) v[k] = sm[swB(t | (k << 8))];
    {
        u64 c2 = CC[0], s2 = SC[0], n2 = NC[0];
#pragma unroll
        for (int k = 0; k < 16; k++)
            if (!(k & 4)) bfly2(v[k], v[k + 4], c2, s2, n2);
        c2 = CC[1]; s2 = SC[1]; n2 = NC[1];
#pragma unroll
        for (int k = 0; k < 16; k++)
            if (!(k & 8)) bfly2(v[k], v[k + 8], c2, s2, n2);
    }
    // store: tg = key{0..5} | mid<<6 | key{6..11}<<12 ; coalesced (lanes=tg0..4)
    {
        int k5  = (t >> 5) & 1;
        int c11b = k5 ^ ((tfixB >> 5) & 1);
        unsigned mid = ((tfixB >> 6) & 0x3F) ^ (c11b ? 0x3Fu : 0u);
        int ob = b * NSTATE + ((t & 63) | (mid << 6) | (((t >> 6) & 3) << 12));
#pragma unroll
        for (int k = 0; k < 16; k++)
            dst[ob + (k << 14)] = v[k];
    }
}

// ---------------------------------------------------------------------------
// Pass C: L1 RY bits {0, 5..11} + P2 scatter + modulus/invnorm -> out.
// ---------------------------------------------------------------------------
__global__ void __launch_bounds__(256, 3)
passC(const float* __restrict__ p1, PermM P, const u64* __restrict__ src,
      float* __restrict__ outF)
{
    extern __shared__ u64 sm[];            // 4096 u64 = 32 KB
    __shared__ float sq[54];
    __shared__ u64 C1[4], S1[4], N1[4];    // bits 5..8
    __shared__ u64 C2[4], S2[4], N2[4];    // bits 0,9,10,11

    int t  = threadIdx.x;
    int b  = blockIdx.x >> 6;
    int ch = blockIdx.x & 63;              // index bits 12..17
    int base = b * NSTATE + (ch << 12);

    u64 v[16];
#pragma unroll
    for (int k = 0; k < 16; k++)
        v[k] = src[base + ((t & 31) | (k << 5) | ((t >> 5) << 9))];  // coalesced

    if (t < 54) sq[t] = p1[t];
    __syncthreads();

    if (t < 4) {                           // bit 5+t, wire 12-t
        float s, c; sincosf(0.5f * sq[(12 - t) * 3 + 1], &s, &c);
        C1[t] = pk(c, c); S1[t] = pk(s, s); N1[t] = pk(-s, -s);
    } else if (t < 8) {
        int j = t - 4;
        int q = (j == 0) ? 0 : (8 + j);    // bits 0,9,10,11
        float s, c; sincosf(0.5f * sq[(17 - q) * 3 + 1], &s, &c);
        C2[j] = pk(c, c); S2[j] = pk(s, s); N2[j] = pk(-s, -s);
    }
    __syncthreads();

    // levels bits 5..8 (k bits 0..3)
#pragma unroll
    for (int kb = 0; kb < 4; kb++) {
        int m = 1 << kb;
        u64 c2 = C1[kb], s2 = S1[kb], n2 = N1[kb];
#pragma unroll
        for (int k = 0; k < 16; k++)
            if (!(k & m)) bfly2(v[k], v[k + m], c2, s2, n2);
    }
#pragma unroll
    for (int k = 0; k < 16; k++)
        sm[swC((t & 31) | (k << 5) | ((t >> 5) << 9))] = v[k];
    __syncthreads();

    // re-own: e = (k&1) | t<<1 | (k>>1)<<9 ; levels on bits 0,9,10,11
#pragma unroll
    for (int k = 0; k < 16; k++)
        v[k] = sm[swC((k & 1) | (t << 1) | ((k >> 1) << 9))];
#pragma unroll
    for (int kb = 0; kb < 4; kb++) {
        int m = 1 << kb;
        u64 c2 = C2[kb], s2 = S2[kb], n2 = N2[kb];
#pragma unroll
        for (int k = 0; k < 16; k++)
            if (!(k & m)) bfly2(v[k], v[k + m], c2, s2, n2);
    }

    // P2 scatter + modulus
    unsigned tb = 0;
#pragma unroll
    for (int j = 0; j < 6; j++)
        if ((ch >> j) & 1) tb ^= P.m[12 + j];
#pragma unroll
    for (int p = 1; p < 9; p++)            // e bits 1..8 = t bits 0..7
        if ((t >> (p - 1)) & 1) tb ^= P.m[p];
    float inv = g_invnorm[b];
    int bb = b * NSTATE;
#pragma unroll
    for (int k = 0; k < 16; k++) {
        unsigned tg = tb;
        if (k & 1) tg ^= P.m[0];
        if (k & 2) tg ^= P.m[9];
        if (k & 4) tg ^= P.m[10];
        if (k & 8) tg ^= P.m[11];
        float ax, ay; up(v[k], ax, ay);
        outF[bb + tg] = sqrtf(fmaf(ax, ax, ay * ay)) * inv;
    }
}

__global__ void norm_kernel() {
    int b = threadIdx.x;
    if (b < NB) {
        float s = 0.f;
        for (int i = 0; i < NCHK; i++) s += g_partial[b * NCHK + i];
        g_invnorm[b] = 1.0f / sqrtf(s);
    }
}

// ---------------------------------------------------------------------------
// Host side
// ---------------------------------------------------------------------------
static PermM makePerm(int l) {
    PermM P;
    for (int p = 0; p < 18; p++) {
        unsigned idx = 1u << p;
        for (int i = 0; i < 18; i++) {
            int c  = (i + l) % 18;
            int t  = (i + l + 1) % 18;
            int cb = 17 - c;
            int tb = 17 - t;
            idx ^= ((idx >> cb) & 1u) << tb;
        }
        P.m[p] = idx;
    }
    return P;
}

extern "C" void kernel_launch(void* const* d_in, const int* in_sizes, int n_in,
                              void* d_out, int out_size)
{
    const float* x      = (const float*)d_in[0];
    const float* params = (const float*)d_in[1];
    if (n_in >= 2 && in_sizes[0] < in_sizes[1]) {  // defensive input-order guard
        x      = (const float*)d_in[1];
        params = (const float*)d_in[0];
    }

    cudaFuncSetAttribute(passA, cudaFuncAttributeMaxDynamicSharedMemorySize, CHUNK * 8);
    cudaFuncSetAttribute(passB, cudaFuncAttributeMaxDynamicSharedMemorySize, CHUNK * 8);
    cudaFuncSetAttribute(passC, cudaFuncAttributeMaxDynamicSharedMemorySize, CHUNK * 8);

    PermM P0 = makePerm(0);
    PermM P1 = makePerm(1);

    u64* sa = nullptr; u64* sb = nullptr;
    cudaGetSymbolAddress((void**)&sa, g_sa);
    cudaGetSymbolAddress((void**)&sb, g_sb);

    passA<<<NB * NCHK, 256, CHUNK * 8>>>(x, params, sa);
    norm_kernel<<<1, 32>>>();
    passB<<<NB * NCHK, 256, CHUNK * 8>>>(params, params + 54, P0, sa, sb);
    passC<<<NB * NCHK, 256, CHUNK * 8>>>(params + 54, P1, sb, (float*)d_out);
}